// round 1
// baseline (speedup 1.0000x reference)
#include <cuda_runtime.h>

#define TT  131072
#define INW 60
#define HH  14
#define FULLM 0xFFFFFFFFu

// Scratch (static __device__ — no allocation per harness rules)
__device__ float2 g_xw0[TT * 28 + 32];   // [T][28] packed (gate j, gate j+28), +1 step pad for prefetch
__device__ float  g_h2[TT * HH];         // layer-2 hidden per step

__device__ __forceinline__ float fast_sigmoid(float x) {
    float e = __expf(-x);                 // MUFU.EX2-based, ~2 ulp
    return __fdividef(1.0f, 1.0f + e);    // MUFU.RCP-based
}

// ---------------- Kernel 1: xw0[t] = x[t] @ W_ih0^T + b_ih0 (parallel over T) ----------------
__global__ void xproj_kernel(const float* __restrict__ x,
                             const float* __restrict__ W,
                             const float* __restrict__ b) {
    int tid = blockIdx.x * blockDim.x + threadIdx.x;
    if (tid >= TT * 28) return;
    int j = tid % 28;
    int t = tid / 28;
    const float* xr = x + t * INW;
    const float* wa = W + j * INW;
    const float* wb = W + (j + 28) * INW;
    float a  = b[j];
    float bb = b[j + 28];
#pragma unroll
    for (int k = 0; k < INW; k++) {
        float xv = __ldg(xr + k);
        a  = fmaf(xv, __ldg(wa + k), a);
        bb = fmaf(xv, __ldg(wb + k), bb);
    }
    g_xw0[t * 28 + j] = make_float2(a, bb);
}

// ---------------- Kernel 2: the sequential 3-layer LSTM scan (single warp) ----------------
__global__ void __launch_bounds__(32, 1)
lstm_seq_kernel(const float* __restrict__ h0in, const float* __restrict__ c0in,
                const float* __restrict__ Whh0, const float* __restrict__ bhh0,
                const float* __restrict__ Wih1, const float* __restrict__ Whh1,
                const float* __restrict__ bih1, const float* __restrict__ bhh1,
                const float* __restrict__ Wih2, const float* __restrict__ Whh2,
                const float* __restrict__ bih2, const float* __restrict__ bhh2) {
    // sW[a][k][j] = (W[j][k], W[j+28][k]) : a = {Whh0, Wih1, Whh1, Wih2, Whh2}
    __shared__ float2 sW[5][HH][28];
    __shared__ float2 sB[3][28];

    const int j = threadIdx.x;  // 0..31
    {
        const float* Wsrc[5] = {Whh0, Wih1, Whh1, Wih2, Whh2};
        for (int a = 0; a < 5; a++) {
            const float* Wp = Wsrc[a];
            for (int idx = j; idx < HH * 28; idx += 32) {
                int kk = idx / 28, jj = idx % 28;
                sW[a][kk][jj] = make_float2(Wp[jj * HH + kk], Wp[(jj + 28) * HH + kk]);
            }
        }
        if (j < 28) {
            sB[0][j] = make_float2(bhh0[j], bhh0[j + 28]);
            sB[1][j] = make_float2(bih1[j] + bhh1[j], bih1[j + 28] + bhh1[j + 28]);
            sB[2][j] = make_float2(bih2[j] + bhh2[j], bih2[j + 28] + bhh2[j + 28]);
        }
    }
    __syncwarp();

    const int  jj   = (j < 28) ? j : 27;   // lanes 28..31 shadow lane 27 for mem ops
    const int  kidx = j % 14;              // row of (h,c) this lane tracks
    const bool isg  = (j < 14);            // lane's B-gate is g (tanh) vs o (sigmoid)

    // Replicated hidden state (every lane holds all 14 per layer)
    float h0r[HH], h1r[HH], h2r[HH];
#pragma unroll
    for (int k = 0; k < HH; k++) {
        h0r[k] = h0in[k];
        h1r[k] = h0in[HH + k];
        h2r[k] = h0in[2 * HH + k];
    }
    float c0v = c0in[kidx];
    float c1v = c0in[HH + kidx];
    float c2v = c0in[2 * HH + kidx];

    const float2 b0 = sB[0][jj];
    const float2 b1 = sB[1][jj];
    const float2 b2 = sB[2][jj];

    float2 xp = g_xw0[jj];

#pragma unroll 1
    for (int t = 0; t < TT; t++) {
        float2 xpn = g_xw0[(t + 1) * 28 + jj];  // prefetch (array padded past TT)

        // ---------------- layer 0 ----------------
        {
            float a0 = b0.x + xp.x, a1 = 0.f, q0 = b0.y + xp.y, q1 = 0.f;
#pragma unroll
            for (int k = 0; k < HH; k += 2) {
                float2 w0 = sW[0][k][jj];
                float2 w1 = sW[0][k + 1][jj];
                a0 = fmaf(h0r[k],     w0.x, a0);  q0 = fmaf(h0r[k],     w0.y, q0);
                a1 = fmaf(h0r[k + 1], w1.x, a1);  q1 = fmaf(h0r[k + 1], w1.y, q1);
            }
            float a  = a0 + a1;
            float bb = q0 + q1;
            float sA = fast_sigmoid(a);
            float xs = isg ? (bb + bb) : bb;
            float s  = fast_sigmoid(xs);
            float sB_ = isg ? fmaf(2.f, s, -1.f) : s;  // tanh(g) or sigmoid(o)
            float iv = __shfl_sync(FULLM, sA,  kidx);
            float fv = __shfl_sync(FULLM, sA,  kidx + 14);
            float gv = __shfl_sync(FULLM, sB_, kidx);
            float ov = __shfl_sync(FULLM, sB_, kidx + 14);
            c0v = fmaf(fv, c0v, iv * gv);
            float tc = fmaf(2.f, fast_sigmoid(c0v + c0v), -1.f);  // tanh(c)
            float hn = ov * tc;
#pragma unroll
            for (int k = 0; k < HH; k++) h0r[k] = __shfl_sync(FULLM, hn, k);
        }

        // ---------------- layer 1 ----------------
        {
            float a0 = b1.x, a1 = 0.f, q0 = b1.y, q1 = 0.f;
#pragma unroll
            for (int k = 0; k < HH; k += 2) {
                float2 w0 = sW[1][k][jj];
                float2 w1 = sW[1][k + 1][jj];
                a0 = fmaf(h0r[k],     w0.x, a0);  q0 = fmaf(h0r[k],     w0.y, q0);
                a1 = fmaf(h0r[k + 1], w1.x, a1);  q1 = fmaf(h0r[k + 1], w1.y, q1);
            }
#pragma unroll
            for (int k = 0; k < HH; k += 2) {
                float2 w0 = sW[2][k][jj];
                float2 w1 = sW[2][k + 1][jj];
                a0 = fmaf(h1r[k],     w0.x, a0);  q0 = fmaf(h1r[k],     w0.y, q0);
                a1 = fmaf(h1r[k + 1], w1.x, a1);  q1 = fmaf(h1r[k + 1], w1.y, q1);
            }
            float a  = a0 + a1;
            float bb = q0 + q1;
            float sA = fast_sigmoid(a);
            float xs = isg ? (bb + bb) : bb;
            float s  = fast_sigmoid(xs);
            float sB_ = isg ? fmaf(2.f, s, -1.f) : s;
            float iv = __shfl_sync(FULLM, sA,  kidx);
            float fv = __shfl_sync(FULLM, sA,  kidx + 14);
            float gv = __shfl_sync(FULLM, sB_, kidx);
            float ov = __shfl_sync(FULLM, sB_, kidx + 14);
            c1v = fmaf(fv, c1v, iv * gv);
            float tc = fmaf(2.f, fast_sigmoid(c1v + c1v), -1.f);
            float hn = ov * tc;
#pragma unroll
            for (int k = 0; k < HH; k++) h1r[k] = __shfl_sync(FULLM, hn, k);
        }

        // ---------------- layer 2 ----------------
        {
            float a0 = b2.x, a1 = 0.f, q0 = b2.y, q1 = 0.f;
#pragma unroll
            for (int k = 0; k < HH; k += 2) {
                float2 w0 = sW[3][k][jj];
                float2 w1 = sW[3][k + 1][jj];
                a0 = fmaf(h1r[k],     w0.x, a0);  q0 = fmaf(h1r[k],     w0.y, q0);
                a1 = fmaf(h1r[k + 1], w1.x, a1);  q1 = fmaf(h1r[k + 1], w1.y, q1);
            }
#pragma unroll
            for (int k = 0; k < HH; k += 2) {
                float2 w0 = sW[4][k][jj];
                float2 w1 = sW[4][k + 1][jj];
                a0 = fmaf(h2r[k],     w0.x, a0);  q0 = fmaf(h2r[k],     w0.y, q0);
                a1 = fmaf(h2r[k + 1], w1.x, a1);  q1 = fmaf(h2r[k + 1], w1.y, q1);
            }
            float a  = a0 + a1;
            float bb = q0 + q1;
            float sA = fast_sigmoid(a);
            float xs = isg ? (bb + bb) : bb;
            float s  = fast_sigmoid(xs);
            float sB_ = isg ? fmaf(2.f, s, -1.f) : s;
            float iv = __shfl_sync(FULLM, sA,  kidx);
            float fv = __shfl_sync(FULLM, sA,  kidx + 14);
            float gv = __shfl_sync(FULLM, sB_, kidx);
            float ov = __shfl_sync(FULLM, sB_, kidx + 14);
            c2v = fmaf(fv, c2v, iv * gv);
            float tc = fmaf(2.f, fast_sigmoid(c2v + c2v), -1.f);
            float hn = ov * tc;
            if (j < 14) g_h2[t * HH + j] = hn;  // lane j holds row j
#pragma unroll
            for (int k = 0; k < HH; k++) h2r[k] = __shfl_sync(FULLM, hn, k);
        }

        xp = xpn;
    }
}

// ---------------- Kernel 3: out = relu(relu(h2) @ W_lin^T + b_lin) (parallel over T) ----------------
__global__ void outproj_kernel(const float* __restrict__ Wlin,
                               const float* __restrict__ blin,
                               float* __restrict__ out) {
    int t = blockIdx.x * blockDim.x + threadIdx.x;
    if (t >= TT) return;
    float hv[HH];
#pragma unroll
    for (int k = 0; k < HH; k++) hv[k] = fmaxf(g_h2[t * HH + k], 0.f);
#pragma unroll
    for (int o = 0; o < 7; o++) {
        float acc = blin[o];
#pragma unroll
        for (int k = 0; k < HH; k++) acc = fmaf(hv[k], Wlin[o * HH + k], acc);
        out[t * 7 + o] = fmaxf(acc, 0.f);
    }
}

extern "C" void kernel_launch(void* const* d_in, const int* in_sizes, int n_in,
                              void* d_out, int out_size) {
    const float* x    = (const float*)d_in[0];
    const float* h0   = (const float*)d_in[1];
    const float* c0   = (const float*)d_in[2];
    const float* Wih0 = (const float*)d_in[3];
    const float* Whh0 = (const float*)d_in[4];
    const float* bih0 = (const float*)d_in[5];
    const float* bhh0 = (const float*)d_in[6];
    const float* Wih1 = (const float*)d_in[7];
    const float* Whh1 = (const float*)d_in[8];
    const float* bih1 = (const float*)d_in[9];
    const float* bhh1 = (const float*)d_in[10];
    const float* Wih2 = (const float*)d_in[11];
    const float* Whh2 = (const float*)d_in[12];
    const float* bih2 = (const float*)d_in[13];
    const float* bhh2 = (const float*)d_in[14];
    const float* Wlin = (const float*)d_in[15];
    const float* blin = (const float*)d_in[16];
    float* out = (float*)d_out;

    int n1 = TT * 28;
    xproj_kernel<<<(n1 + 255) / 256, 256>>>(x, Wih0, bih0);
    lstm_seq_kernel<<<1, 32>>>(h0, c0, Whh0, bhh0,
                               Wih1, Whh1, bih1, bhh1,
                               Wih2, Whh2, bih2, bhh2);
    outproj_kernel<<<(TT + 255) / 256, 256>>>(Wlin, blin, out);
}

// round 2
// speedup vs baseline: 1.4505x; 1.4505x over previous
#include <cuda_runtime.h>

#define TT  131072
#define INW 60
#define HH  14
#define FULLM 0xFFFFFFFFu

// Scratch (static __device__ — no allocation per harness rules)
__device__ float2 g_xw0[TT * 28 + 96];   // [T][28] packed (gate j, gate j+28), padded for prefetch
__device__ float  g_h2[TT * HH];         // layer-2 hidden per step

__device__ __forceinline__ float ex2f(float x) {
    float r; asm("ex2.approx.f32 %0, %1;" : "=f"(r) : "f"(x)); return r;
}
__device__ __forceinline__ float rcpf(float x) {
    float r; asm("rcp.approx.f32 %0, %1;" : "=f"(r) : "f"(x)); return r;
}
// Packed 2-wide FMA (sm_100+): ptxas never emits this from C++, only via PTX.
__device__ __forceinline__ float2 ffma2(float2 a, float2 b, float2 c) {
    union { float2 f; unsigned long long u; } ua, ub, uc, ud;
    ua.f = a; ub.f = b; uc.f = c;
    asm("fma.rn.f32x2 %0, %1, %2, %3;" : "=l"(ud.u) : "l"(ua.u), "l"(ub.u), "l"(uc.u));
    return ud.f;
}

// ---------------- Kernel 1: xw0[t] = x[t] @ W_ih0^T + b_ih0 (parallel over T) ----------------
__global__ void xproj_kernel(const float* __restrict__ x,
                             const float* __restrict__ W,
                             const float* __restrict__ b) {
    int tid = blockIdx.x * blockDim.x + threadIdx.x;
    if (tid >= TT * 28) return;
    int j = tid % 28;
    int t = tid / 28;
    const float* xr = x + t * INW;
    const float* wa = W + j * INW;
    const float* wb = W + (j + 28) * INW;
    float a  = b[j];
    float bb = b[j + 28];
#pragma unroll
    for (int k = 0; k < INW; k++) {
        float xv = __ldg(xr + k);
        a  = fmaf(xv, __ldg(wa + k), a);
        bb = fmaf(xv, __ldg(wb + k), bb);
    }
    g_xw0[t * 28 + j] = make_float2(a, bb);
}

// ---------------- Scan-kernel helpers ----------------
// accA/accQ: packed partial sums over (even k, odd k); 7-deep FFMA2 chain per matrix
__device__ __forceinline__ void mv7(float2& accA, float2& accQ,
                                    const float2 (&wA)[7], const float2 (&wQ)[7],
                                    const float2 (&hp)[7]) {
#pragma unroll
    for (int k = 0; k < 7; k++) {
        accA = ffma2(hp[k], wA[k], accA);
        accQ = ffma2(hp[k], wQ[k], accQ);
    }
}

// gates -> activations -> c update -> new h scalar (valid on lanes 0..13 as h[lane])
__device__ __forceinline__ float act_h(float a, float q, float& c, int kidx,
                                       float kq, float mm, float aa) {
    const float KA = -1.4426950408889634f;   // -log2(e)
    float sA = rcpf(1.f + ex2f(a * KA));                 // sigmoid (i or f)
    float sQ = fmaf(rcpf(1.f + ex2f(q * kq)), mm, aa);   // tanh (g) or sigmoid (o)
    float iv = __shfl_sync(FULLM, sA, kidx);
    float fv = __shfl_sync(FULLM, sA, kidx + 14);
    float gv = __shfl_sync(FULLM, sQ, kidx);
    float ov = __shfl_sync(FULLM, sQ, kidx + 14);
    c = fmaf(fv, c, iv * gv);
    float tc = fmaf(rcpf(1.f + ex2f(c * -2.8853900817779268f)), 2.f, -1.f);  // tanh(c)
    return ov * tc;
}

__device__ __forceinline__ void bcast(float2 (&hp)[7], float hn) {
#pragma unroll
    for (int k = 0; k < 7; k++) {
        hp[k].x = __shfl_sync(FULLM, hn, 2 * k);
        hp[k].y = __shfl_sync(FULLM, hn, 2 * k + 1);
    }
}

// ---------------- Kernel 2: sequential 3-layer LSTM scan, single warp, layer-pipelined ----------------
__global__ void __launch_bounds__(32, 1)
lstm_seq_kernel(const float* __restrict__ h0in, const float* __restrict__ c0in,
                const float* __restrict__ Whh0, const float* __restrict__ bhh0,
                const float* __restrict__ Wih1, const float* __restrict__ Whh1,
                const float* __restrict__ bih1, const float* __restrict__ bhh1,
                const float* __restrict__ Wih2, const float* __restrict__ Whh2,
                const float* __restrict__ bih2, const float* __restrict__ bhh2) {
    const int  j    = threadIdx.x;
    const int  jj   = (j < 28) ? j : 27;   // lanes 28..31 shadow lane 27
    const int  kidx = j % 14;
    const bool isg  = (j < 14);
    const float kq = isg ? -2.8853900817779268f : -1.4426950408889634f;
    const float mm = isg ? 2.f : 1.f;
    const float aa = isg ? -1.f : 0.f;

    // ---- all weights in registers, packed (w[j][2k], w[j][2k+1]) ----
    float2 w0A[7],  w0Q[7];    // Whh0
    float2 w1iA[7], w1iQ[7];   // Wih1
    float2 w1hA[7], w1hQ[7];   // Whh1
    float2 w2iA[7], w2iQ[7];   // Wih2
    float2 w2hA[7], w2hQ[7];   // Whh2
#pragma unroll
    for (int k = 0; k < 7; k++) {
        w0A[k]  = *(const float2*)&Whh0[jj * HH + 2 * k];
        w0Q[k]  = *(const float2*)&Whh0[(jj + 28) * HH + 2 * k];
        w1iA[k] = *(const float2*)&Wih1[jj * HH + 2 * k];
        w1iQ[k] = *(const float2*)&Wih1[(jj + 28) * HH + 2 * k];
        w1hA[k] = *(const float2*)&Whh1[jj * HH + 2 * k];
        w1hQ[k] = *(const float2*)&Whh1[(jj + 28) * HH + 2 * k];
        w2iA[k] = *(const float2*)&Wih2[jj * HH + 2 * k];
        w2iQ[k] = *(const float2*)&Wih2[(jj + 28) * HH + 2 * k];
        w2hA[k] = *(const float2*)&Whh2[jj * HH + 2 * k];
        w2hQ[k] = *(const float2*)&Whh2[(jj + 28) * HH + 2 * k];
    }
    const float b0A = bhh0[jj],              b0Q = bhh0[jj + 28];
    const float b1A = bih1[jj] + bhh1[jj],   b1Q = bih1[jj + 28] + bhh1[jj + 28];
    const float b2A = bih2[jj] + bhh2[jj],   b2Q = bih2[jj + 28] + bhh2[jj + 28];

    // ---- state: packed replicated h per layer, distributed c ----
    float2 h0p[7], h1p[7], h2p[7];
#pragma unroll
    for (int k = 0; k < 7; k++) {
        h0p[k] = *(const float2*)&h0in[2 * k];
        h1p[k] = *(const float2*)&h0in[HH + 2 * k];
        h2p[k] = *(const float2*)&h0in[2 * HH + 2 * k];
    }
    float c0v = c0in[kidx], c1v = c0in[HH + kidx], c2v = c0in[2 * HH + kidx];

    // ---- prologue: fill the 3-deep layer pipeline ----
    float2 xcur = g_xw0[jj];                       // step 0
    {   // i=0 : L0(0)
        float2 aA = make_float2(b0A + xcur.x, 0.f), aQ = make_float2(b0Q + xcur.y, 0.f);
        mv7(aA, aQ, w0A, w0Q, h0p);
        float hn0 = act_h(aA.x + aA.y, aQ.x + aQ.y, c0v, kidx, kq, mm, aa);
        bcast(h0p, hn0);
    }
    xcur = g_xw0[28 + jj];                         // step 1
    {   // i=1 : L0(1) + L1(0)
        float2 aA = make_float2(b0A + xcur.x, 0.f), aQ = make_float2(b0Q + xcur.y, 0.f);
        float2 bA = make_float2(b1A, 0.f),          bQ = make_float2(b1Q, 0.f);
        mv7(bA, bQ, w1iA, w1iQ, h0p);   // reads h0(0) before overwrite
        mv7(bA, bQ, w1hA, w1hQ, h1p);
        mv7(aA, aQ, w0A, w0Q, h0p);
        float hn0 = act_h(aA.x + aA.y, aQ.x + aQ.y, c0v, kidx, kq, mm, aa);
        float hn1 = act_h(bA.x + bA.y, bQ.x + bQ.y, c1v, kidx, kq, mm, aa);
        bcast(h0p, hn0);
        bcast(h1p, hn1);
    }

    xcur = g_xw0[2 * 28 + jj];
    float2 xnxt = g_xw0[3 * 28 + jj];

    // ---- steady state: body t computes L0(t), L1(t-1), L2(t-2) — mutually independent ----
#pragma unroll 1
    for (int t = 2; t < TT; t++) {
        float2 xnew = g_xw0[(t + 2) * 28 + jj];    // prefetch 2 steps ahead (L2-resident)

        float2 aA = make_float2(b0A + xcur.x, 0.f), aQ = make_float2(b0Q + xcur.y, 0.f);
        mv7(aA, aQ, w0A, w0Q, h0p);                // L0(t)

        float2 bA = make_float2(b1A, 0.f), bQ = make_float2(b1Q, 0.f);
        mv7(bA, bQ, w1iA, w1iQ, h0p);              // L1(t-1), reads h0(t-1)
        mv7(bA, bQ, w1hA, w1hQ, h1p);

        float2 cA = make_float2(b2A, 0.f), cQ = make_float2(b2Q, 0.f);
        mv7(cA, cQ, w2iA, w2iQ, h1p);              // L2(t-2), reads h1(t-2)
        mv7(cA, cQ, w2hA, w2hQ, h2p);

        float hn0 = act_h(aA.x + aA.y, aQ.x + aQ.y, c0v, kidx, kq, mm, aa);
        float hn1 = act_h(bA.x + bA.y, bQ.x + bQ.y, c1v, kidx, kq, mm, aa);
        float hn2 = act_h(cA.x + cA.y, cQ.x + cQ.y, c2v, kidx, kq, mm, aa);

        if (j < HH) g_h2[(t - 2) * HH + j] = hn2;

        bcast(h0p, hn0);
        bcast(h1p, hn1);
        bcast(h2p, hn2);

        xcur = xnxt;
        xnxt = xnew;
    }

    // ---- epilogue: drain L1, L2 ----
    {   // i=TT : L1(TT-1) + L2(TT-2)
        float2 bA = make_float2(b1A, 0.f), bQ = make_float2(b1Q, 0.f);
        mv7(bA, bQ, w1iA, w1iQ, h0p);
        mv7(bA, bQ, w1hA, w1hQ, h1p);
        float2 cA = make_float2(b2A, 0.f), cQ = make_float2(b2Q, 0.f);
        mv7(cA, cQ, w2iA, w2iQ, h1p);
        mv7(cA, cQ, w2hA, w2hQ, h2p);
        float hn1 = act_h(bA.x + bA.y, bQ.x + bQ.y, c1v, kidx, kq, mm, aa);
        float hn2 = act_h(cA.x + cA.y, cQ.x + cQ.y, c2v, kidx, kq, mm, aa);
        if (j < HH) g_h2[(TT - 2) * HH + j] = hn2;
        bcast(h1p, hn1);
        bcast(h2p, hn2);
    }
    {   // i=TT+1 : L2(TT-1)
        float2 cA = make_float2(b2A, 0.f), cQ = make_float2(b2Q, 0.f);
        mv7(cA, cQ, w2iA, w2iQ, h1p);
        mv7(cA, cQ, w2hA, w2hQ, h2p);
        float hn2 = act_h(cA.x + cA.y, cQ.x + cQ.y, c2v, kidx, kq, mm, aa);
        if (j < HH) g_h2[(TT - 1) * HH + j] = hn2;
    }
}

// ---------------- Kernel 3: out = relu(relu(h2) @ W_lin^T + b_lin) (parallel over T) ----------------
__global__ void outproj_kernel(const float* __restrict__ Wlin,
                               const float* __restrict__ blin,
                               float* __restrict__ out) {
    int t = blockIdx.x * blockDim.x + threadIdx.x;
    if (t >= TT) return;
    float hv[HH];
#pragma unroll
    for (int k = 0; k < HH; k++) hv[k] = fmaxf(g_h2[t * HH + k], 0.f);
#pragma unroll
    for (int o = 0; o < 7; o++) {
        float acc = blin[o];
#pragma unroll
        for (int k = 0; k < HH; k++) acc = fmaf(hv[k], Wlin[o * HH + k], acc);
        out[t * 7 + o] = fmaxf(acc, 0.f);
    }
}

extern "C" void kernel_launch(void* const* d_in, const int* in_sizes, int n_in,
                              void* d_out, int out_size) {
    const float* x    = (const float*)d_in[0];
    const float* h0   = (const float*)d_in[1];
    const float* c0   = (const float*)d_in[2];
    const float* Wih0 = (const float*)d_in[3];
    const float* Whh0 = (const float*)d_in[4];
    const float* bih0 = (const float*)d_in[5];
    const float* bhh0 = (const float*)d_in[6];
    const float* Wih1 = (const float*)d_in[7];
    const float* Whh1 = (const float*)d_in[8];
    const float* bih1 = (const float*)d_in[9];
    const float* bhh1 = (const float*)d_in[10];
    const float* Wih2 = (const float*)d_in[11];
    const float* Whh2 = (const float*)d_in[12];
    const float* bih2 = (const float*)d_in[13];
    const float* bhh2 = (const float*)d_in[14];
    const float* Wlin = (const float*)d_in[15];
    const float* blin = (const float*)d_in[16];
    float* out = (float*)d_out;

    int n1 = TT * 28;
    xproj_kernel<<<(n1 + 255) / 256, 256>>>(x, Wih0, bih0);
    lstm_seq_kernel<<<1, 32>>>(h0, c0, Whh0, bhh0,
                               Wih1, Whh1, bih1, bhh1,
                               Wih2, Whh2, bih2, bhh2);
    outproj_kernel<<<(TT + 255) / 256, 256>>>(Wlin, blin, out);
}

// round 3
// speedup vs baseline: 1.7084x; 1.1778x over previous
#include <cuda_runtime.h>

#define TT  131072
#define INW 60
#define HH  14
#define FULLM 0xFFFFFFFFu

// Scratch (static __device__ — no allocation per harness rules)
__device__ float2 g_xw0[TT * 28 + 96];   // [T][28] packed (gate j, gate j+28), padded for prefetch
__device__ float  g_h2[TT * HH];         // layer-2 hidden per step

__device__ __forceinline__ float ex2f(float x) {
    float r; asm("ex2.approx.f32 %0, %1;" : "=f"(r) : "f"(x)); return r;
}
__device__ __forceinline__ float rcpf(float x) {
    float r; asm("rcp.approx.f32 %0, %1;" : "=f"(r) : "f"(x)); return r;
}
__device__ __forceinline__ float tanh_ap(float x) {
    float r; asm("tanh.approx.f32 %0, %1;" : "=f"(r) : "f"(x)); return r;
}
// Packed 2-wide FMA / ADD (sm_100+): ptxas never emits these from C++, only via PTX.
__device__ __forceinline__ float2 ffma2(float2 a, float2 b, float2 c) {
    union { float2 f; unsigned long long u; } ua, ub, uc, ud;
    ua.f = a; ub.f = b; uc.f = c;
    asm("fma.rn.f32x2 %0, %1, %2, %3;" : "=l"(ud.u) : "l"(ua.u), "l"(ub.u), "l"(uc.u));
    return ud.f;
}
__device__ __forceinline__ float2 fadd2(float2 a, float2 b) {
    union { float2 f; unsigned long long u; } ua, ub, uc;
    ua.f = a; ub.f = b;
    asm("add.rn.f32x2 %0, %1, %2;" : "=l"(uc.u) : "l"(ua.u), "l"(ub.u));
    return uc.f;
}

// ---------------- Kernel 1: xw0[t] = x[t] @ W_ih0^T + b_ih0 (parallel over T) ----------------
__global__ void xproj_kernel(const float* __restrict__ x,
                             const float* __restrict__ W,
                             const float* __restrict__ b) {
    int tid = blockIdx.x * blockDim.x + threadIdx.x;
    if (tid >= TT * 28) return;
    int j = tid % 28;
    int t = tid / 28;
    const float* xr = x + t * INW;
    const float* wa = W + j * INW;
    const float* wb = W + (j + 28) * INW;
    float a  = b[j];
    float bb = b[j + 28];
#pragma unroll
    for (int k = 0; k < INW; k++) {
        float xv = __ldg(xr + k);
        a  = fmaf(xv, __ldg(wa + k), a);
        bb = fmaf(xv, __ldg(wb + k), bb);
    }
    g_xw0[t * 28 + j] = make_float2(a, bb);
}

// ---------------- Scan-kernel helpers ----------------
__device__ __forceinline__ void mv7(float2& accA, float2& accQ,
                                    const float2 (&wA)[7], const float2 (&wQ)[7],
                                    const float2 (&hp)[7]) {
#pragma unroll
    for (int k = 0; k < 7; k++) {
        accA = ffma2(hp[k], wA[k], accA);
        accQ = ffma2(hp[k], wQ[k], accQ);
    }
}

// gates -> activations -> c update -> new h scalar (valid on lanes 0..13 as h[lane])
// sA: EXACT sigmoid (i / f gates — protects the c accumulation path).
// sQ: MUFU.TANH-based: tanh(g) for lanes<14, sigmoid(o)=0.5*tanh(q/2)+0.5 for lanes>=14.
__device__ __forceinline__ float act_h(float a, float q, float& c, int kidx,
                                       float kq2, float mm2, float aa2) {
    const float KA = -1.4426950408889634f;   // -log2(e)
    float sA = rcpf(1.f + ex2f(a * KA));
    float sQ = fmaf(tanh_ap(q * kq2), mm2, aa2);
    float iv = __shfl_sync(FULLM, sA, kidx);
    float fv = __shfl_sync(FULLM, sA, kidx + 14);
    float gv = __shfl_sync(FULLM, sQ, kidx);
    float ov = __shfl_sync(FULLM, sQ, kidx + 14);
    c = fmaf(fv, c, iv * gv);
    return ov * tanh_ap(c);
}

__device__ __forceinline__ void bcast(float2 (&hp)[7], float hn) {
#pragma unroll
    for (int k = 0; k < 7; k++) {
        hp[k].x = __shfl_sync(FULLM, hn, 2 * k);
        hp[k].y = __shfl_sync(FULLM, hn, 2 * k + 1);
    }
}

// ---------------- Kernel 2: sequential 3-layer LSTM scan, single warp, layer-pipelined ----------------
__global__ void __launch_bounds__(32, 1)
lstm_seq_kernel(const float* __restrict__ h0in, const float* __restrict__ c0in,
                const float* __restrict__ Whh0, const float* __restrict__ bhh0,
                const float* __restrict__ Wih1, const float* __restrict__ Whh1,
                const float* __restrict__ bih1, const float* __restrict__ bhh1,
                const float* __restrict__ Wih2, const float* __restrict__ Whh2,
                const float* __restrict__ bih2, const float* __restrict__ bhh2) {
    const int  j    = threadIdx.x;
    const int  jj   = (j < 28) ? j : 27;   // lanes 28..31 shadow lane 27
    const int  kidx = j % 14;
    const bool isg  = (j < 14);
    const float kq2 = isg ? 1.0f : 0.5f;   // tanh(g)  vs  sigmoid(o)=0.5*tanh(q/2)+0.5
    const float mm2 = isg ? 1.0f : 0.5f;
    const float aa2 = isg ? 0.0f : 0.5f;

    // ---- all weights in registers, packed (w[j][2k], w[j][2k+1]) ----
    float2 w0A[7],  w0Q[7];    // Whh0
    float2 w1iA[7], w1iQ[7];   // Wih1
    float2 w1hA[7], w1hQ[7];   // Whh1
    float2 w2iA[7], w2iQ[7];   // Wih2
    float2 w2hA[7], w2hQ[7];   // Whh2
#pragma unroll
    for (int k = 0; k < 7; k++) {
        w0A[k]  = *(const float2*)&Whh0[jj * HH + 2 * k];
        w0Q[k]  = *(const float2*)&Whh0[(jj + 28) * HH + 2 * k];
        w1iA[k] = *(const float2*)&Wih1[jj * HH + 2 * k];
        w1iQ[k] = *(const float2*)&Wih1[(jj + 28) * HH + 2 * k];
        w1hA[k] = *(const float2*)&Whh1[jj * HH + 2 * k];
        w1hQ[k] = *(const float2*)&Whh1[(jj + 28) * HH + 2 * k];
        w2iA[k] = *(const float2*)&Wih2[jj * HH + 2 * k];
        w2iQ[k] = *(const float2*)&Wih2[(jj + 28) * HH + 2 * k];
        w2hA[k] = *(const float2*)&Whh2[jj * HH + 2 * k];
        w2hQ[k] = *(const float2*)&Whh2[(jj + 28) * HH + 2 * k];
    }
    const float b0A = bhh0[jj],              b0Q = bhh0[jj + 28];
    const float b1A = bih1[jj] + bhh1[jj],   b1Q = bih1[jj + 28] + bhh1[jj + 28];
    const float b2A = bih2[jj] + bhh2[jj],   b2Q = bih2[jj + 28] + bhh2[jj + 28];

    // ---- state: packed replicated h per layer, distributed c ----
    float2 h0p[7], h1p[7], h2p[7];
#pragma unroll
    for (int k = 0; k < 7; k++) {
        h0p[k] = *(const float2*)&h0in[2 * k];
        h1p[k] = *(const float2*)&h0in[HH + 2 * k];
        h2p[k] = *(const float2*)&h0in[2 * HH + 2 * k];
    }
    float c0v = c0in[kidx], c1v = c0in[HH + kidx], c2v = c0in[2 * HH + kidx];

    // ---- prologue: fill the 3-deep layer pipeline ----
    float2 xcur = g_xw0[jj];                       // step 0
    {   // i=0 : L0(0)
        float2 aA = make_float2(b0A + xcur.x, 0.f), aQ = make_float2(b0Q + xcur.y, 0.f);
        mv7(aA, aQ, w0A, w0Q, h0p);
        float hn0 = act_h(aA.x + aA.y, aQ.x + aQ.y, c0v, kidx, kq2, mm2, aa2);
        bcast(h0p, hn0);
    }
    xcur = g_xw0[28 + jj];                         // step 1
    {   // i=1 : L0(1) + L1(0)
        float2 aA = make_float2(b0A + xcur.x, 0.f), aQ = make_float2(b0Q + xcur.y, 0.f);
        float2 bA = make_float2(b1A, 0.f),          bQ = make_float2(b1Q, 0.f);
        mv7(bA, bQ, w1iA, w1iQ, h0p);   // reads h0(0) before overwrite
        mv7(bA, bQ, w1hA, w1hQ, h1p);
        mv7(aA, aQ, w0A, w0Q, h0p);
        float hn0 = act_h(aA.x + aA.y, aQ.x + aQ.y, c0v, kidx, kq2, mm2, aa2);
        float hn1 = act_h(bA.x + bA.y, bQ.x + bQ.y, c1v, kidx, kq2, mm2, aa2);
        bcast(h0p, hn0);
        bcast(h1p, hn1);
    }

    xcur = g_xw0[2 * 28 + jj];

    // ---- steady state: body t computes L0(t), L1(t-1), L2(t-2) — mutually independent ----
#pragma unroll 1
    for (int t = 2; t < TT; t++) {
        float2 xnxt = g_xw0[(t + 1) * 28 + jj];    // prefetch next step (L2-resident)

        // L0(t): single 7-deep chain (+bias)
        float2 aA = make_float2(b0A + xcur.x, 0.f), aQ = make_float2(b0Q + xcur.y, 0.f);
        mv7(aA, aQ, w0A, w0Q, h0p);

        // L1(t-1): two independent 7-deep chains (ih on h0(t-1), hh on h1(t-2))
        float2 bAi = make_float2(b1A, 0.f), bQi = make_float2(b1Q, 0.f);
        float2 bAh = make_float2(0.f, 0.f), bQh = make_float2(0.f, 0.f);
        mv7(bAi, bQi, w1iA, w1iQ, h0p);
        mv7(bAh, bQh, w1hA, w1hQ, h1p);

        // L2(t-2): two independent 7-deep chains
        float2 cAi = make_float2(b2A, 0.f), cQi = make_float2(b2Q, 0.f);
        float2 cAh = make_float2(0.f, 0.f), cQh = make_float2(0.f, 0.f);
        mv7(cAi, cQi, w2iA, w2iQ, h1p);
        mv7(cAh, cQh, w2hA, w2hQ, h2p);

        float2 bA = fadd2(bAi, bAh), bQ = fadd2(bQi, bQh);
        float2 cA = fadd2(cAi, cAh), cQ = fadd2(cQi, cQh);

        float hn0 = act_h(aA.x + aA.y, aQ.x + aQ.y, c0v, kidx, kq2, mm2, aa2);
        float hn1 = act_h(bA.x + bA.y, bQ.x + bQ.y, c1v, kidx, kq2, mm2, aa2);
        float hn2 = act_h(cA.x + cA.y, cQ.x + cQ.y, c2v, kidx, kq2, mm2, aa2);

        if (j < HH) g_h2[(t - 2) * HH + j] = hn2;

        bcast(h0p, hn0);
        bcast(h1p, hn1);
        bcast(h2p, hn2);

        xcur = xnxt;
    }

    // ---- epilogue: drain L1, L2 ----
    {   // i=TT : L1(TT-1) + L2(TT-2)
        float2 bA = make_float2(b1A, 0.f), bQ = make_float2(b1Q, 0.f);
        mv7(bA, bQ, w1iA, w1iQ, h0p);
        mv7(bA, bQ, w1hA, w1hQ, h1p);
        float2 cA = make_float2(b2A, 0.f), cQ = make_float2(b2Q, 0.f);
        mv7(cA, cQ, w2iA, w2iQ, h1p);
        mv7(cA, cQ, w2hA, w2hQ, h2p);
        float hn1 = act_h(bA.x + bA.y, bQ.x + bQ.y, c1v, kidx, kq2, mm2, aa2);
        float hn2 = act_h(cA.x + cA.y, cQ.x + cQ.y, c2v, kidx, kq2, mm2, aa2);
        if (j < HH) g_h2[(TT - 2) * HH + j] = hn2;
        bcast(h1p, hn1);
        bcast(h2p, hn2);
    }
    {   // i=TT+1 : L2(TT-1)
        float2 cA = make_float2(b2A, 0.f), cQ = make_float2(b2Q, 0.f);
        mv7(cA, cQ, w2iA, w2iQ, h1p);
        mv7(cA, cQ, w2hA, w2hQ, h2p);
        float hn2 = act_h(cA.x + cA.y, cQ.x + cQ.y, c2v, kidx, kq2, mm2, aa2);
        if (j < HH) g_h2[(TT - 1) * HH + j] = hn2;
    }
}

// ---------------- Kernel 3: out = relu(relu(h2) @ W_lin^T + b_lin) (parallel over T) ----------------
__global__ void outproj_kernel(const float* __restrict__ Wlin,
                               const float* __restrict__ blin,
                               float* __restrict__ out) {
    int t = blockIdx.x * blockDim.x + threadIdx.x;
    if (t >= TT) return;
    float hv[HH];
#pragma unroll
    for (int k = 0; k < HH; k++) hv[k] = fmaxf(g_h2[t * HH + k], 0.f);
#pragma unroll
    for (int o = 0; o < 7; o++) {
        float acc = blin[o];
#pragma unroll
        for (int k = 0; k < HH; k++) acc = fmaf(hv[k], Wlin[o * HH + k], acc);
        out[t * 7 + o] = fmaxf(acc, 0.f);
    }
}

extern "C" void kernel_launch(void* const* d_in, const int* in_sizes, int n_in,
                              void* d_out, int out_size) {
    const float* x    = (const float*)d_in[0];
    const float* h0   = (const float*)d_in[1];
    const float* c0   = (const float*)d_in[2];
    const float* Wih0 = (const float*)d_in[3];
    const float* Whh0 = (const float*)d_in[4];
    const float* bih0 = (const float*)d_in[5];
    const float* bhh0 = (const float*)d_in[6];
    const float* Wih1 = (const float*)d_in[7];
    const float* Whh1 = (const float*)d_in[8];
    const float* bih1 = (const float*)d_in[9];
    const float* bhh1 = (const float*)d_in[10];
    const float* Wih2 = (const float*)d_in[11];
    const float* Whh2 = (const float*)d_in[12];
    const float* bih2 = (const float*)d_in[13];
    const float* bhh2 = (const float*)d_in[14];
    const float* Wlin = (const float*)d_in[15];
    const float* blin = (const float*)d_in[16];
    float* out = (float*)d_out;

    int n1 = TT * 28;
    xproj_kernel<<<(n1 + 255) / 256, 256>>>(x, Wih0, bih0);
    lstm_seq_kernel<<<1, 32>>>(h0, c0, Whh0, bhh0,
                               Wih1, Whh1, bih1, bhh1,
                               Wih2, Whh2, bih2, bhh2);
    outproj_kernel<<<(TT + 255) / 256, 256>>>(Wlin, blin, out);
}